// round 1
// baseline (speedup 1.0000x reference)
#include <cuda_runtime.h>
#include <cstdint>

// Problem constants
#define H_DIM 512
#define W_DIM 512
#define CIN   3
#define COUT  32
#define NB    16

// Tiling
#define TW 32           // threads in x
#define TH 4            // rows per block
#define PX 4            // pixels per thread along w
#define BW (TW*PX)      // 128-wide tile
#define SSTRIDE 132     // smem row stride (floats), multiple of 4 for LDS.128 alignment

__device__ __forceinline__ unsigned long long pk2(float lo, float hi) {
    unsigned long long r;
    asm("mov.b64 %0, {%1, %2};" : "=l"(r) : "r"(__float_as_uint(lo)), "r"(__float_as_uint(hi)));
    return r;
}
__device__ __forceinline__ void fma2(unsigned long long& d, unsigned long long a, unsigned long long w) {
    asm("fma.rn.f32x2 %0, %1, %2, %0;" : "+l"(d) : "l"(a), "l"(w));
}
__device__ __forceinline__ void unpk2(unsigned long long v, float& lo, float& hi) {
    unsigned int a, b;
    asm("mov.b64 {%0, %1}, %2;" : "=r"(a), "=r"(b) : "l"(v));
    lo = __uint_as_float(a);
    hi = __uint_as_float(b);
}

__global__ __launch_bounds__(TW*TH, 3)
void pconv3x3_kernel(const float* __restrict__ x,
                     const float* __restrict__ Wm,
                     const float* __restrict__ bias,
                     float* __restrict__ out)
{
    __shared__ float xs[CIN][TH + 2][SSTRIDE];
    __shared__ unsigned long long ws[COUT][28];  // duplicated-pair effective weights, tap = c*9 + i*3 + j
    __shared__ unsigned long long bs[COUT];

    const int tid = threadIdx.y * TW + threadIdx.x;
    const int w0 = blockIdx.x * BW;
    const int h0 = blockIdx.y * TH;
    const int b  = blockIdx.z;

    // ---- effective-weight prep (3x3 conv form; center = -sum of the 8 taps) ----
    // COORDS order k for (i,j): (0,0),(1,0),(2,0),(0,1),(2,1),(0,2),(1,2),(2,2)
    const int kmap[9] = {0, 3, 5,  1, -1, 6,  2, 4, 7};  // kmap[i*3+j]
    for (int t = tid; t < COUT * 27; t += TW * TH) {
        const int o   = t / 27;
        const int rem = t % 27;
        const int c   = rem / 9;
        const int ij  = rem % 9;
        float wv;
        if (ij == 4) {
            float s = 0.f;
            #pragma unroll
            for (int k = 0; k < 8; k++) s += Wm[o * 24 + k * 3 + c];
            wv = -s;
        } else {
            wv = Wm[o * 24 + kmap[ij] * 3 + c];
        }
        ws[o][rem] = pk2(wv, wv);
    }
    if (tid < COUT) bs[tid] = pk2(bias[tid], bias[tid]);

    // ---- cooperative x tile load (with zero padding) ----
    const float* xb = x + (size_t)b * CIN * H_DIM * W_DIM;
    for (int idx = tid; idx < CIN * (TH + 2) * (BW + 2); idx += TW * TH) {
        const int c   = idx / ((TH + 2) * (BW + 2));
        const int rem = idx % ((TH + 2) * (BW + 2));
        const int r   = rem / (BW + 2);
        const int s   = rem % (BW + 2);
        const int gh  = h0 + r - 1;
        const int gw  = w0 + s - 1;
        float v = 0.f;
        if ((unsigned)gh < H_DIM && (unsigned)gw < W_DIM)
            v = xb[((size_t)c * H_DIM + gh) * W_DIM + gw];
        xs[c][r][s] = v;
    }
    __syncthreads();

    // ---- gather 3x6 window per channel into packed f32x2 registers ----
    // v[0..5] covers cols w-1 .. w+4 for the thread's 4 pixels
    // pe[0]=(v0,v1) pe[1]=(v2,v3) pe[2]=(v4,v5)   po[0]=(v1,v2) po[1]=(v3,v4)
    unsigned long long pe[CIN][3][3], po[CIN][3][2];
    #pragma unroll
    for (int c = 0; c < CIN; c++) {
        #pragma unroll
        for (int r = 0; r < 3; r++) {
            const float* p = &xs[c][threadIdx.y + r][threadIdx.x * PX];  // 16B aligned
            const float4 a  = *(const float4*)p;
            const float2 b2 = *(const float2*)(p + 4);
            pe[c][r][0] = pk2(a.x, a.y);
            pe[c][r][1] = pk2(a.z, a.w);
            pe[c][r][2] = pk2(b2.x, b2.y);
            po[c][r][0] = pk2(a.y, a.z);
            po[c][r][1] = pk2(a.w, b2.x);
        }
    }

    const int h    = h0 + threadIdx.y;
    const int wcol = w0 + threadIdx.x * PX;
    float* ob = out + (size_t)b * COUT * H_DIM * W_DIM + (size_t)h * W_DIM + wcol;

    // ---- main loop over output channels: 54 FFMA2 + weight LDS per o ----
    #pragma unroll 1
    for (int o = 0; o < COUT; o++) {
        unsigned long long acc0 = bs[o];  // pixels 0,1
        unsigned long long acc1 = bs[o];  // pixels 2,3
        const unsigned long long* wr = ws[o];
        #pragma unroll
        for (int c = 0; c < CIN; c++) {
            #pragma unroll
            for (int r = 0; r < 3; r++) {
                unsigned long long wv;
                wv = wr[c * 9 + r * 3 + 0]; fma2(acc0, pe[c][r][0], wv); fma2(acc1, pe[c][r][1], wv);
                wv = wr[c * 9 + r * 3 + 1]; fma2(acc0, po[c][r][0], wv); fma2(acc1, po[c][r][1], wv);
                wv = wr[c * 9 + r * 3 + 2]; fma2(acc0, pe[c][r][1], wv); fma2(acc1, pe[c][r][2], wv);
            }
        }
        float f0, f1, f2, f3;
        unpk2(acc0, f0, f1);
        unpk2(acc1, f2, f3);
        *(float4*)(ob + (size_t)o * H_DIM * W_DIM) = make_float4(f0, f1, f2, f3);
    }
}

extern "C" void kernel_launch(void* const* d_in, const int* in_sizes, int n_in,
                              void* d_out, int out_size)
{
    const float* x  = (const float*)d_in[0];  // [16,3,512,512]
    const float* Wm = (const float*)d_in[1];  // [32,24]
    const float* bi = (const float*)d_in[2];  // [32]
    float* out = (float*)d_out;               // [16,32,512,512]

    dim3 block(TW, TH, 1);
    dim3 grid(W_DIM / BW, H_DIM / TH, NB);    // (4, 128, 16)
    pconv3x3_kernel<<<grid, block>>>(x, Wm, bi, out);
}

// round 2
// speedup vs baseline: 1.0638x; 1.0638x over previous
#include <cuda_runtime.h>
#include <cstdint>

// Problem constants
#define H_DIM 512
#define W_DIM 512
#define CIN   3
#define COUT  32
#define NB    16

// Tiling
#define TW 32           // threads in x
#define TH 4            // rows per block
#define PX 4            // pixels per thread along w
#define BW (TW*PX)      // 128-wide tile
#define SSTRIDE 132     // smem row stride (floats)

typedef unsigned long long ull;

__device__ __forceinline__ ull pk2(float lo, float hi) {
    ull r;
    asm("mov.b64 %0, {%1, %2};" : "=l"(r) : "r"(__float_as_uint(lo)), "r"(__float_as_uint(hi)));
    return r;
}
__device__ __forceinline__ void fma2(ull& d, ull a, ull w) {
    asm("fma.rn.f32x2 %0, %1, %2, %0;" : "+l"(d) : "l"(a), "l"(w));
}
__device__ __forceinline__ void unpk2(ull v, float& lo, float& hi) {
    unsigned int a, b;
    asm("mov.b64 {%0, %1}, %2;" : "=r"(a), "=r"(b) : "l"(v));
    lo = __uint_as_float(a);
    hi = __uint_as_float(b);
}

__global__ __launch_bounds__(TW*TH, 4)
void pconv3x3_kernel(const float* __restrict__ x,
                     const float* __restrict__ Wm,
                     const float* __restrict__ bias,
                     float* __restrict__ out)
{
    __shared__ float xs[CIN][TH + 2][SSTRIDE];
    __shared__ __align__(16) ull ws[COUT][28];  // tap = c*9 + r*3 + j; [27] = pad for LDS.128
    __shared__ ull bs[COUT];

    const int tid = threadIdx.y * TW + threadIdx.x;
    const int w0 = blockIdx.x * BW;
    const int h0 = blockIdx.y * TH;
    const int b  = blockIdx.z;

    // ---- effective-weight prep (3x3 conv form; center = -sum of the 8 taps) ----
    // COORDS order k for (i,j): (0,0),(1,0),(2,0),(0,1),(2,1),(0,2),(1,2),(2,2)
    const int kmap[9] = {0, 3, 5,  1, -1, 6,  2, 4, 7};  // kmap[r*3+j]
    for (int t = tid; t < COUT * 27; t += TW * TH) {
        const int o   = t / 27;
        const int rem = t % 27;
        const int c   = rem / 9;
        const int ij  = rem % 9;
        float wv;
        if (ij == 4) {
            float s = 0.f;
            #pragma unroll
            for (int k = 0; k < 8; k++) s += Wm[o * 24 + k * 3 + c];
            wv = -s;
        } else {
            wv = Wm[o * 24 + kmap[ij] * 3 + c];
        }
        ws[o][rem] = pk2(wv, wv);
    }
    if (tid < COUT) {
        ws[tid][27] = 0ull;  // pad so LDS.128 of pair 13 reads defined data
        bs[tid] = pk2(bias[tid], bias[tid]);
    }

    // ---- cooperative x tile load (with zero padding) ----
    const float* xb = x + (size_t)b * CIN * H_DIM * W_DIM;
    for (int idx = tid; idx < CIN * (TH + 2) * (BW + 2); idx += TW * TH) {
        const int c   = idx / ((TH + 2) * (BW + 2));
        const int rem = idx % ((TH + 2) * (BW + 2));
        const int r   = rem / (BW + 2);
        const int s   = rem % (BW + 2);
        const int gh  = h0 + r - 1;
        const int gw  = w0 + s - 1;
        float v = 0.f;
        if ((unsigned)gh < H_DIM && (unsigned)gw < W_DIM)
            v = xb[((size_t)c * H_DIM + gh) * W_DIM + gw];
        xs[c][r][s] = v;
    }
    __syncthreads();

    // ---- gather 3x6 window per channel into packed f32x2 registers ----
    // v[0..5] covers cols w-1 .. w+4 for the thread's 4 pixels
    // pe[0]=(v0,v1) pe[1]=(v2,v3) pe[2]=(v4,v5)   po[0]=(v1,v2) po[1]=(v3,v4)
    ull pe[CIN][3][3], po[CIN][3][2];
    #pragma unroll
    for (int c = 0; c < CIN; c++) {
        #pragma unroll
        for (int r = 0; r < 3; r++) {
            const float* p = &xs[c][threadIdx.y + r][threadIdx.x * PX];  // 16B aligned
            const float4 a  = *(const float4*)p;
            const float2 b2 = *(const float2*)(p + 4);
            pe[c][r][0] = pk2(a.x, a.y);
            pe[c][r][1] = pk2(a.z, a.w);
            pe[c][r][2] = pk2(b2.x, b2.y);
            po[c][r][0] = pk2(a.y, a.z);
            po[c][r][1] = pk2(a.w, b2.x);
        }
    }

    const int h    = h0 + threadIdx.y;
    const int wcol = w0 + threadIdx.x * PX;
    float* ob = out + (size_t)b * COUT * H_DIM * W_DIM + (size_t)h * W_DIM + wcol;

    // ---- main loop over output channels ----
    // Per o: 14 LDS.128 weight-pair loads + 54 FFMA2. Unroll 2 so the next
    // channel's weight loads overlap the current FMA chain.
    #pragma unroll 2
    for (int o = 0; o < COUT; o++) {
        ull acc0 = bs[o];  // pixels 0,1
        ull acc1 = bs[o];  // pixels 2,3
        const ulonglong2* wr2 = (const ulonglong2*)ws[o];

        #pragma unroll
        for (int tp = 0; tp < 14; tp++) {
            const ulonglong2 wp = wr2[tp];
            // tap 2*tp
            {
                const int t = 2 * tp;
                const int c = t / 9, rr = (t % 9) / 3, j = t % 3;
                if (j == 0)      { fma2(acc0, pe[c][rr][0], wp.x); fma2(acc1, pe[c][rr][1], wp.x); }
                else if (j == 1) { fma2(acc0, po[c][rr][0], wp.x); fma2(acc1, po[c][rr][1], wp.x); }
                else             { fma2(acc0, pe[c][rr][1], wp.x); fma2(acc1, pe[c][rr][2], wp.x); }
            }
            // tap 2*tp+1 (skip the pad tap 27)
            if (tp < 13) {
                const int t = 2 * tp + 1;
                const int c = t / 9, rr = (t % 9) / 3, j = t % 3;
                if (j == 0)      { fma2(acc0, pe[c][rr][0], wp.y); fma2(acc1, pe[c][rr][1], wp.y); }
                else if (j == 1) { fma2(acc0, po[c][rr][0], wp.y); fma2(acc1, po[c][rr][1], wp.y); }
                else             { fma2(acc0, pe[c][rr][1], wp.y); fma2(acc1, pe[c][rr][2], wp.y); }
            }
        }

        float f0, f1, f2, f3;
        unpk2(acc0, f0, f1);
        unpk2(acc1, f2, f3);
        *(float4*)(ob + (size_t)o * H_DIM * W_DIM) = make_float4(f0, f1, f2, f3);
    }
}

extern "C" void kernel_launch(void* const* d_in, const int* in_sizes, int n_in,
                              void* d_out, int out_size)
{
    const float* x  = (const float*)d_in[0];  // [16,3,512,512]
    const float* Wm = (const float*)d_in[1];  // [32,24]
    const float* bi = (const float*)d_in[2];  // [32]
    float* out = (float*)d_out;               // [16,32,512,512]

    dim3 block(TW, TH, 1);
    dim3 grid(W_DIM / BW, H_DIM / TH, NB);    // (4, 128, 16)
    pconv3x3_kernel<<<grid, block>>>(x, Wm, bi, out);
}

// round 3
// speedup vs baseline: 1.2262x; 1.1527x over previous
#include <cuda_runtime.h>
#include <cstdint>

// Problem constants
#define H_DIM 512
#define W_DIM 512
#define CIN   3
#define COUT  32
#define NB    16

// Tiling
#define TW 32           // threads in x
#define TH 4            // rows per block
#define PX 4            // pixels per thread along w
#define BW (TW*PX)      // 128-wide tile
#define SSTRIDE 132     // smem row stride (floats)
#define NTHREADS (TW*TH)

typedef unsigned long long ull;

// Prepped weights: per o, 28 slots: [0]=bias pair, [1..27]=taps 0..26 (tap=c*9+r*3+j)
__device__ __align__(16) ull g_ws[COUT * 28];

__device__ __forceinline__ ull pk2(float lo, float hi) {
    ull r;
    asm("mov.b64 %0, {%1, %2};" : "=l"(r) : "r"(__float_as_uint(lo)), "r"(__float_as_uint(hi)));
    return r;
}
__device__ __forceinline__ void fma2(ull& d, ull a, ull w) {
    asm("fma.rn.f32x2 %0, %1, %2, %0;" : "+l"(d) : "l"(a), "l"(w));
}
__device__ __forceinline__ void unpk2(ull v, float& lo, float& hi) {
    unsigned int a, b;
    asm("mov.b64 {%0, %1}, %2;" : "=r"(a), "=r"(b) : "l"(v));
    lo = __uint_as_float(a);
    hi = __uint_as_float(b);
}

// ---- one-time weight prep: 896 slots ----
__global__ void prep_weights_kernel(const float* __restrict__ Wm,
                                    const float* __restrict__ bias)
{
    const int s = blockIdx.x * blockDim.x + threadIdx.x;
    if (s >= COUT * 28) return;
    const int o    = s / 28;
    const int slot = s % 28;
    // COORDS order k for ij=(r*3+j): (0,0),(1,0),(2,0),(0,1),(2,1),(0,2),(1,2),(2,2)
    const int kmap[9] = {0, 3, 5,  1, -1, 6,  2, 4, 7};
    float wv;
    if (slot == 0) {
        wv = bias[o];
    } else {
        const int t  = slot - 1;
        const int c  = t / 9;
        const int ij = t % 9;
        if (ij == 4) {
            float ssum = 0.f;
            #pragma unroll
            for (int k = 0; k < 8; k++) ssum += Wm[o * 24 + k * 3 + c];
            wv = -ssum;
        } else {
            wv = Wm[o * 24 + kmap[ij] * 3 + c];
        }
    }
    g_ws[o * 28 + slot] = pk2(wv, wv);
}

__global__ __launch_bounds__(NTHREADS, 4)
void pconv3x3_kernel(const float* __restrict__ x,
                     float* __restrict__ out)
{
    __shared__ float xs[CIN][TH + 2][SSTRIDE];
    __shared__ __align__(16) ull ws[COUT * 28];

    const int tid = threadIdx.y * TW + threadIdx.x;
    const int w0 = blockIdx.x * BW;
    const int h0 = blockIdx.y * TH;
    const int b  = blockIdx.z;

    // ---- weight smem copy: 448 ulonglong2, 128 threads -> 4 iters ----
    {
        const ulonglong2* src = (const ulonglong2*)g_ws;
        ulonglong2* dst = (ulonglong2*)ws;
        #pragma unroll
        for (int i = 0; i < 4; i++) {
            const int idx = tid + i * NTHREADS;
            if (idx < COUT * 14) dst[idx] = src[idx];
        }
    }

    // ---- tile load, div/mod free: 3 ch x 6 rows x 130 cols ----
    // thread tid covers col tid; tid<2 also covers cols 128,129.
    const float* xb = x + (size_t)b * CIN * H_DIM * W_DIM;
    {
        const int gw = w0 + tid - 1;
        const bool okw = (unsigned)gw < W_DIM;
        const int gw2 = w0 + tid + (NTHREADS - 1);   // second col (tid<2 only)
        const bool okw2 = (tid < 2) && ((unsigned)gw2 < W_DIM);
        #pragma unroll
        for (int c = 0; c < CIN; c++) {
            const float* pc = xb + (size_t)c * H_DIM * W_DIM;
            #pragma unroll
            for (int r = 0; r < TH + 2; r++) {
                const int gh = h0 + r - 1;
                const bool okh = (unsigned)gh < H_DIM;
                float v = 0.f;
                if (okh && okw) v = pc[gh * W_DIM + gw];
                xs[c][r][tid] = v;
                float v2 = 0.f;
                if (okh && okw2) v2 = pc[gh * W_DIM + gw2];
                if (tid < 2) xs[c][r][NTHREADS + tid] = v2;
            }
        }
    }
    __syncthreads();

    // ---- gather 3x6 window per channel into packed f32x2 registers ----
    // v[0..5] covers cols w-1 .. w+4 for this thread's 4 pixels
    ull pe[CIN][3][3], po[CIN][3][2];
    #pragma unroll
    for (int c = 0; c < CIN; c++) {
        #pragma unroll
        for (int r = 0; r < 3; r++) {
            const float* p = &xs[c][threadIdx.y + r][threadIdx.x * PX];  // 16B aligned
            const float4 a  = *(const float4*)p;
            const float2 b2 = *(const float2*)(p + 4);
            pe[c][r][0] = pk2(a.x, a.y);
            pe[c][r][1] = pk2(a.z, a.w);
            pe[c][r][2] = pk2(b2.x, b2.y);
            po[c][r][0] = pk2(a.y, a.z);
            po[c][r][1] = pk2(a.w, b2.x);
        }
    }

    const int h    = h0 + threadIdx.y;
    const int wcol = w0 + threadIdx.x * PX;
    float* ob = out + (size_t)b * COUT * H_DIM * W_DIM + (size_t)h * W_DIM + wcol;

    // ---- main loop: per o, 14 LDS.128 (bias+27 taps) + 54 FFMA2 + STG.128 ----
    #pragma unroll 2
    for (int o = 0; o < COUT; o++) {
        const ulonglong2* wr2 = (const ulonglong2*)(ws + o * 28);

        // pair 0: (bias, tap0)
        ulonglong2 wp = wr2[0];
        ull acc0 = wp.x;
        ull acc1 = wp.x;
        // tap0: c=0, r=0, j=0
        fma2(acc0, pe[0][0][0], wp.y);
        fma2(acc1, pe[0][0][1], wp.y);

        #pragma unroll
        for (int p = 1; p < 14; p++) {
            wp = wr2[p];
            {   // tap 2p-1
                const int t = 2 * p - 1;
                const int c = t / 9, rr = (t % 9) / 3, j = t % 3;
                if (j == 0)      { fma2(acc0, pe[c][rr][0], wp.x); fma2(acc1, pe[c][rr][1], wp.x); }
                else if (j == 1) { fma2(acc0, po[c][rr][0], wp.x); fma2(acc1, po[c][rr][1], wp.x); }
                else             { fma2(acc0, pe[c][rr][1], wp.x); fma2(acc1, pe[c][rr][2], wp.x); }
            }
            {   // tap 2p
                const int t = 2 * p;
                const int c = t / 9, rr = (t % 9) / 3, j = t % 3;
                if (j == 0)      { fma2(acc0, pe[c][rr][0], wp.y); fma2(acc1, pe[c][rr][1], wp.y); }
                else if (j == 1) { fma2(acc0, po[c][rr][0], wp.y); fma2(acc1, po[c][rr][1], wp.y); }
                else             { fma2(acc0, pe[c][rr][1], wp.y); fma2(acc1, pe[c][rr][2], wp.y); }
            }
        }

        float f0, f1, f2, f3;
        unpk2(acc0, f0, f1);
        unpk2(acc1, f2, f3);
        *(float4*)(ob + (size_t)o * H_DIM * W_DIM) = make_float4(f0, f1, f2, f3);
    }
}

extern "C" void kernel_launch(void* const* d_in, const int* in_sizes, int n_in,
                              void* d_out, int out_size)
{
    const float* x  = (const float*)d_in[0];  // [16,3,512,512]
    const float* Wm = (const float*)d_in[1];  // [32,24]
    const float* bi = (const float*)d_in[2];  // [32]
    float* out = (float*)d_out;               // [16,32,512,512]

    prep_weights_kernel<<<7, 128>>>(Wm, bi);

    dim3 block(TW, TH, 1);
    dim3 grid(W_DIM / BW, H_DIM / TH, NB);    // (4, 128, 16)
    pconv3x3_kernel<<<grid, block>>>(x, out);
}

// round 6
// speedup vs baseline: 1.6739x; 1.3651x over previous
#include <cuda_runtime.h>
#include <cstdint>

#define H_DIM 512
#define W_DIM 512
#define CIN   3
#define COUT  32
#define NB    16
#define HW    (H_DIM * W_DIM)

#define NTHREADS 128
// smem x-tile layout: xs[c*824 + r*136 + s], c<3, r<6, s<130
#define RSTRIDE 136
#define CSTRIDE 824
#define XS_FLOATS 2496

// Prepped B matrix: g_wB[k*32 + o] = tf32(Weff[o][PERM[k]]), 0 for pad taps
__device__ uint32_t g_wB[32 * 32];

// k -> tap id (c*9+i*3+j); -1 = pad (weight forced to 0).
__device__ __constant__ int c_PERM[32] = {
    0, 3, 6, 9,   12, 15, 18, 21,
    1, 4, 7, 10,  13, 16, 19, 22,
    2, 5, 8, 11,  14, 17, 20, 23,
    24, 25, 26, -1,  -1, -1, -1, -1
};

// smem float-offset for each k (c*824 + i*136 + j).
// Pad taps -> offset 0: their B weight is exactly 0.0f and the x tile holds
// only finite floats, so 0*finite = 0 contribution. Max address over all
// threads/tiles = 1922 + 3*136 + 7 + 7*16 = 2449 < 2496 (in bounds).
__device__ __constant__ int c_OFFS[32] = {
    0, 136, 272, 824,    960, 1096, 1648, 1784,
    1, 137, 273, 825,    961, 1097, 1649, 1785,
    2, 138, 274, 826,    962, 1098, 1650, 1786,
    1920, 1921, 1922, 0,  0, 0, 0, 0
};

__device__ __forceinline__ uint32_t cvt_tf32(float f) {
    uint32_t u;
    asm("cvt.rna.tf32.f32 %0, %1;" : "=r"(u) : "f"(f));
    return u;
}

// ---- one-time weight prep ----
__global__ void prep_weights_kernel(const float* __restrict__ Wm)
{
    const int s = blockIdx.x * blockDim.x + threadIdx.x;
    if (s >= 32 * 32) return;
    const int k = s / 32;
    const int o = s % 32;
    const int tap = c_PERM[k];
    float wv = 0.f;
    if (tap >= 0) {
        const int c  = tap / 9;
        const int ij = tap % 9;
        // COORDS order for ij=(i*3+j): (0,0),(1,0),(2,0),(0,1),(2,1),(0,2),(1,2),(2,2)
        const int kmap[9] = {0, 3, 5,  1, -1, 6,  2, 4, 7};
        if (ij == 4) {
            float ssum = 0.f;
            #pragma unroll
            for (int q = 0; q < 8; q++) ssum += Wm[o * 24 + q * 3 + c];
            wv = -ssum;
        } else {
            wv = Wm[o * 24 + kmap[ij] * 3 + c];
        }
    }
    g_wB[k * 32 + o] = cvt_tf32(wv);
}

__device__ __forceinline__ float lds_f32(uint32_t addr) {
    float v;
    asm volatile("ld.shared.f32 %0, [%1];" : "=f"(v) : "r"(addr));
    return v;
}

__device__ __forceinline__ void mma_tf32(float* c, uint32_t a0, uint32_t a1,
                                         uint32_t a2, uint32_t a3,
                                         uint32_t b0, uint32_t b1) {
    asm volatile(
        "mma.sync.aligned.m16n8k8.row.col.f32.tf32.tf32.f32 "
        "{%0,%1,%2,%3}, {%4,%5,%6,%7}, {%8,%9}, {%0,%1,%2,%3};"
        : "+f"(c[0]), "+f"(c[1]), "+f"(c[2]), "+f"(c[3])
        : "r"(a0), "r"(a1), "r"(a2), "r"(a3), "r"(b0), "r"(b1));
}

__global__ __launch_bounds__(NTHREADS, 5)
void pconv_mma_kernel(const float* __restrict__ x,
                      const float* __restrict__ bias,
                      float* __restrict__ out)
{
    __shared__ float xs[XS_FLOATS];

    const int tid  = threadIdx.x;
    const int lane = tid & 31;
    const int hr   = tid >> 5;      // warp id = output row within tile
    const int g    = lane >> 2;     // groupID
    const int tig  = lane & 3;      // thread-in-group

    const int w0 = blockIdx.x * 128;
    const int h0 = blockIdx.y * 4;
    const int b  = blockIdx.z;

    // ---- x tile load: 3 ch x 6 rows x 130 cols, zero halo ----
    const float* xb = x + (size_t)b * CIN * HW;
    {
        const int gw  = w0 + tid - 1;
        const bool okw = (unsigned)gw < W_DIM;
        const int gw2 = w0 + tid + (NTHREADS - 1);
        const bool okw2 = (tid < 2) && ((unsigned)gw2 < W_DIM);
        #pragma unroll
        for (int c = 0; c < CIN; c++) {
            const float* pc = xb + (size_t)c * HW;
            #pragma unroll
            for (int r = 0; r < 6; r++) {
                const int gh = h0 + r - 1;
                const bool okh = (unsigned)gh < H_DIM;
                float v = 0.f;
                if (okh && okw) v = pc[gh * W_DIM + gw];
                xs[c * CSTRIDE + r * RSTRIDE + tid] = v;
                float v2 = 0.f;
                if (okh && okw2) v2 = pc[gh * W_DIM + gw2];
                if (tid < 2) xs[c * CSTRIDE + r * RSTRIDE + NTHREADS + tid] = v2;
            }
        }
    }

    // ---- B fragments (weights), held in registers ----
    uint32_t Bf[4][4][2];
    #pragma unroll
    for (int nt = 0; nt < 4; nt++)
        #pragma unroll
        for (int ks = 0; ks < 4; ks++) {
            Bf[nt][ks][0] = g_wB[(8 * ks + tig) * 32 + nt * 8 + g];
            Bf[nt][ks][1] = g_wB[(8 * ks + 4 + tig) * 32 + nt * 8 + g];
        }

    // ---- bias for this thread's output columns ----
    float bias0[4], bias1[4];
    #pragma unroll
    for (int nt = 0; nt < 4; nt++) {
        bias0[nt] = bias[nt * 8 + tig * 2];
        bias1[nt] = bias[nt * 8 + tig * 2 + 1];
    }

    // ---- A-fragment smem addresses (byte), one per (ks, pair) ----
    uint32_t sbase;
    asm("{ .reg .u64 t; cvta.to.shared.u64 t, %1; cvt.u32.u64 %0, t; }"
        : "=r"(sbase) : "l"(xs));
    uint32_t aaddr[8];
    #pragma unroll
    for (int ks = 0; ks < 4; ks++) {
        #pragma unroll
        for (int p = 0; p < 2; p++) {
            const int k = 8 * ks + 4 * p + tig;
            aaddr[ks * 2 + p] = sbase + 4 * (c_OFFS[k] + hr * RSTRIDE + g);
        }
    }

    // ---- output pointers, one per n-tile ----
    float* op[4];
    #pragma unroll
    for (int nt = 0; nt < 4; nt++)
        op[nt] = out + ((size_t)b * COUT + nt * 8 + tig * 2) * HW
                     + (size_t)(h0 + hr) * W_DIM + w0 + g;

    __syncthreads();

    // ---- 8 tiles of 16 pixels along w ----
    #pragma unroll 1
    for (int t = 0; t < 8; t++) {
        float acc[4][4];
        #pragma unroll
        for (int nt = 0; nt < 4; nt++) {
            acc[nt][0] = bias0[nt];
            acc[nt][1] = bias1[nt];
            acc[nt][2] = bias0[nt];
            acc[nt][3] = bias1[nt];
        }

        #pragma unroll
        for (int ks = 0; ks < 4; ks++) {
            const uint32_t a0 = cvt_tf32(lds_f32(aaddr[ks * 2]));
            const uint32_t a1 = cvt_tf32(lds_f32(aaddr[ks * 2] + 32));
            const uint32_t a2 = cvt_tf32(lds_f32(aaddr[ks * 2 + 1]));
            const uint32_t a3 = cvt_tf32(lds_f32(aaddr[ks * 2 + 1] + 32));
            #pragma unroll
            for (int nt = 0; nt < 4; nt++)
                mma_tf32(acc[nt], a0, a1, a2, a3, Bf[nt][ks][0], Bf[nt][ks][1]);
        }

        #pragma unroll
        for (int nt = 0; nt < 4; nt++) {
            op[nt][0]      = acc[nt][0];
            op[nt][HW]     = acc[nt][1];
            op[nt][8]      = acc[nt][2];
            op[nt][HW + 8] = acc[nt][3];
            op[nt] += 16;
        }
        #pragma unroll
        for (int q = 0; q < 8; q++) aaddr[q] += 64;
    }
}

extern "C" void kernel_launch(void* const* d_in, const int* in_sizes, int n_in,
                              void* d_out, int out_size)
{
    const float* x  = (const float*)d_in[0];  // [16,3,512,512]
    const float* Wm = (const float*)d_in[1];  // [32,24]
    const float* bi = (const float*)d_in[2];  // [32]
    float* out = (float*)d_out;               // [16,32,512,512]

    prep_weights_kernel<<<8, 128>>>(Wm);

    dim3 block(NTHREADS, 1, 1);
    dim3 grid(W_DIM / 128, H_DIM / 4, NB);    // (4, 128, 16)
    pconv_mma_kernel<<<grid, block>>>(x, bi, out);
}

// round 11
// speedup vs baseline: 1.7324x; 1.0350x over previous
#include <cuda_runtime.h>
#include <cstdint>

#define H_DIM 512
#define W_DIM 512
#define CIN   3
#define COUT  32
#define NB    16
#define HW    (H_DIM * W_DIM)

#define NTHREADS 128
// smem x-tile layout: xs[c*824 + r*136 + s], c<3, r<6, s<130
#define RSTRIDE 136
#define CSTRIDE 824
#define XS_FLOATS 2496

// output staging buffer: per warp, 32 channels x 32 px, stride 36 (conflict-free)
#define BUFW 36
#define BUF_PER_WARP (32 * BUFW)   // 1152 floats

// Prepped B matrix: g_wB[k*32 + o] = tf32(Weff[o][PERM[k]]), 0 for pad taps
__device__ uint32_t g_wB[32 * 32];

// k -> tap id (c*9+i*3+j); -1 = pad (weight forced to 0).
__device__ __constant__ int c_PERM[32] = {
    0, 3, 6, 9,   12, 15, 18, 21,
    1, 4, 7, 10,  13, 16, 19, 22,
    2, 5, 8, 11,  14, 17, 20, 23,
    24, 25, 26, -1,  -1, -1, -1, -1
};

// smem float-offset for each k (c*824 + i*136 + j).
// Pad taps -> offset 0 (their B weight is exactly 0.0f; tile data is finite).
__device__ __constant__ int c_OFFS[32] = {
    0, 136, 272, 824,    960, 1096, 1648, 1784,
    1, 137, 273, 825,    961, 1097, 1649, 1785,
    2, 138, 274, 826,    962, 1098, 1650, 1786,
    1920, 1921, 1922, 0,  0, 0, 0, 0
};

__device__ __forceinline__ uint32_t cvt_tf32(float f) {
    uint32_t u;
    asm("cvt.rna.tf32.f32 %0, %1;" : "=r"(u) : "f"(f));
    return u;
}

// ---- one-time weight prep ----
__global__ void prep_weights_kernel(const float* __restrict__ Wm)
{
    const int s = blockIdx.x * blockDim.x + threadIdx.x;
    if (s >= 32 * 32) return;
    const int k = s / 32;
    const int o = s % 32;
    const int tap = c_PERM[k];
    float wv = 0.f;
    if (tap >= 0) {
        const int c  = tap / 9;
        const int ij = tap % 9;
        // COORDS order for ij=(i*3+j): (0,0),(1,0),(2,0),(0,1),(2,1),(0,2),(1,2),(2,2)
        const int kmap[9] = {0, 3, 5,  1, -1, 6,  2, 4, 7};
        if (ij == 4) {
            float ssum = 0.f;
            #pragma unroll
            for (int q = 0; q < 8; q++) ssum += Wm[o * 24 + q * 3 + c];
            wv = -ssum;
        } else {
            wv = Wm[o * 24 + kmap[ij] * 3 + c];
        }
    }
    g_wB[k * 32 + o] = cvt_tf32(wv);
}

__device__ __forceinline__ float lds_f32(uint32_t addr) {
    float v;
    asm volatile("ld.shared.f32 %0, [%1];" : "=f"(v) : "r"(addr));
    return v;
}

__device__ __forceinline__ void mma_tf32(float* c, uint32_t a0, uint32_t a1,
                                         uint32_t a2, uint32_t a3,
                                         uint32_t b0, uint32_t b1) {
    asm volatile(
        "mma.sync.aligned.m16n8k8.row.col.f32.tf32.tf32.f32 "
        "{%0,%1,%2,%3}, {%4,%5,%6,%7}, {%8,%9}, {%0,%1,%2,%3};"
        : "+f"(c[0]), "+f"(c[1]), "+f"(c[2]), "+f"(c[3])
        : "r"(a0), "r"(a1), "r"(a2), "r"(a3), "r"(b0), "r"(b1));
}

__global__ __launch_bounds__(NTHREADS, 5)
void pconv_mma_kernel(const float* __restrict__ x,
                      const float* __restrict__ bias,
                      float* __restrict__ out)
{
    __shared__ float xs[XS_FLOATS];
    __shared__ __align__(16) float obuf[4 * BUF_PER_WARP];

    const int tid  = threadIdx.x;
    const int lane = tid & 31;
    const int hr   = tid >> 5;      // warp id = output row within tile
    const int g    = lane >> 2;     // groupID
    const int tig  = lane & 3;      // thread-in-group

    const int w0 = blockIdx.x * 128;
    const int h0 = blockIdx.y * 4;
    const int b  = blockIdx.z;

    // ---- x tile load: 3 ch x 6 rows x 130 cols, zero halo ----
    const float* xb = x + (size_t)b * CIN * HW;
    {
        const int gw  = w0 + tid - 1;
        const bool okw = (unsigned)gw < W_DIM;
        const int gw2 = w0 + tid + (NTHREADS - 1);
        const bool okw2 = (tid < 2) && ((unsigned)gw2 < W_DIM);
        #pragma unroll
        for (int c = 0; c < CIN; c++) {
            const float* pc = xb + (size_t)c * HW;
            #pragma unroll
            for (int r = 0; r < 6; r++) {
                const int gh = h0 + r - 1;
                const bool okh = (unsigned)gh < H_DIM;
                float v = 0.f;
                if (okh && okw) v = pc[gh * W_DIM + gw];
                xs[c * CSTRIDE + r * RSTRIDE + tid] = v;
                float v2 = 0.f;
                if (okh && okw2) v2 = pc[gh * W_DIM + gw2];
                if (tid < 2) xs[c * CSTRIDE + r * RSTRIDE + NTHREADS + tid] = v2;
            }
        }
    }

    // ---- B fragments (weights), held in registers ----
    uint32_t Bf[4][4][2];
    #pragma unroll
    for (int nt = 0; nt < 4; nt++)
        #pragma unroll
        for (int ks = 0; ks < 4; ks++) {
            Bf[nt][ks][0] = g_wB[(8 * ks + tig) * 32 + nt * 8 + g];
            Bf[nt][ks][1] = g_wB[(8 * ks + 4 + tig) * 32 + nt * 8 + g];
        }

    // ---- bias for this thread's output columns ----
    float bias0[4], bias1[4];
    #pragma unroll
    for (int nt = 0; nt < 4; nt++) {
        bias0[nt] = bias[nt * 8 + tig * 2];
        bias1[nt] = bias[nt * 8 + tig * 2 + 1];
    }

    // ---- A-fragment smem addresses (byte), one per (ks, pair) ----
    uint32_t sbase;
    asm("{ .reg .u64 t; cvta.to.shared.u64 t, %1; cvt.u32.u64 %0, t; }"
        : "=r"(sbase) : "l"(xs));
    uint32_t aaddr[8];
    #pragma unroll
    for (int ks = 0; ks < 4; ks++) {
        #pragma unroll
        for (int p = 0; p < 2; p++) {
            const int k = 8 * ks + 4 * p + tig;
            aaddr[ks * 2 + p] = sbase + 4 * (c_OFFS[k] + hr * RSTRIDE + g);
        }
    }

    // ---- epilogue addressing ----
    float* bw = obuf + hr * BUF_PER_WARP;
    const int chsub = lane >> 3;         // 0..3: channel within cc-group of 4
    const int px4   = 4 * (lane & 7);    // 0..28: pixel quad within 32-px row
    float* p0 = out + (size_t)b * COUT * HW + (size_t)chsub * HW
                    + (size_t)(h0 + hr) * W_DIM + w0 + px4;

    __syncthreads();

    // ---- 4 double-tiles of 32 pixels along w ----
    #pragma unroll 1
    for (int dt = 0; dt < 4; dt++) {
        #pragma unroll
        for (int tt = 0; tt < 2; tt++) {
            float acc[4][4];
            #pragma unroll
            for (int nt = 0; nt < 4; nt++) {
                acc[nt][0] = bias0[nt];
                acc[nt][1] = bias1[nt];
                acc[nt][2] = bias0[nt];
                acc[nt][3] = bias1[nt];
            }

            #pragma unroll
            for (int ks = 0; ks < 4; ks++) {
                const uint32_t a0 = cvt_tf32(lds_f32(aaddr[ks * 2]));
                const uint32_t a1 = cvt_tf32(lds_f32(aaddr[ks * 2] + 32));
                const uint32_t a2 = cvt_tf32(lds_f32(aaddr[ks * 2 + 1]));
                const uint32_t a3 = cvt_tf32(lds_f32(aaddr[ks * 2 + 1] + 32));
                #pragma unroll
                for (int nt = 0; nt < 4; nt++)
                    mma_tf32(acc[nt], a0, a1, a2, a3, Bf[nt][ks][0], Bf[nt][ks][1]);
            }

            // stage to smem: buf[ch][px], stride 36 -> conflict-free
            #pragma unroll
            for (int nt = 0; nt < 4; nt++) {
                float* q = bw + (8 * nt + 2 * tig) * BUFW + 16 * tt + g;
                q[0]        = acc[nt][0];
                q[BUFW]     = acc[nt][1];
                q[8]        = acc[nt][2];
                q[BUFW + 8] = acc[nt][3];
            }

            #pragma unroll
            for (int q = 0; q < 8; q++) aaddr[q] += 64;
        }

        __syncwarp();

        // coalesced store: each 8-lane group emits one full 128B out line.
        // 8 cc-iterations x 4 lane-groups = all 32 channels.
        #pragma unroll
        for (int cc = 0; cc < 8; cc++) {
            const float4 v = *(const float4*)&bw[(4 * cc + chsub) * BUFW + px4];
            __stcs((float4*)(p0 + (size_t)(4 * cc) * HW + dt * 32), v);
        }

        __syncwarp();
    }
}

extern "C" void kernel_launch(void* const* d_in, const int* in_sizes, int n_in,
                              void* d_out, int out_size)
{
    const float* x  = (const float*)d_in[0];  // [16,3,512,512]
    const float* Wm = (const float*)d_in[1];  // [32,24]
    const float* bi = (const float*)d_in[2];  // [32]
    float* out = (float*)d_out;               // [16,32,512,512]

    prep_weights_kernel<<<8, 128>>>(Wm);

    dim3 block(NTHREADS, 1, 1);
    dim3 grid(W_DIM / 128, H_DIM / 4, NB);    // (4, 128, 16)
    pconv_mma_kernel<<<grid, block>>>(x, bi, out);
}